// round 1
// baseline (speedup 1.0000x reference)
#include <cuda_runtime.h>
#include <cuda_bf16.h>

#define FEAT 64
#define MAX_USERS 200000
#define MAX_SPOTS 50000

// Scratch: per-node degree -> inv_sqrt (in-place).
__device__ float g_user_w[MAX_USERS];
__device__ float g_spot_w[MAX_SPOTS];

// ---------------------------------------------------------------------------
// K1: zero the output buffer and the degree scratch.
// ---------------------------------------------------------------------------
__global__ void zero_kernel(float* __restrict__ out, int out_n,
                            float* __restrict__ uw, int n_users,
                            float* __restrict__ sw, int n_spots) {
    int stride = gridDim.x * blockDim.x;
    for (int i = blockIdx.x * blockDim.x + threadIdx.x; i < out_n; i += stride)
        out[i] = 0.0f;
    for (int i = blockIdx.x * blockDim.x + threadIdx.x; i < n_users; i += stride)
        uw[i] = 0.0f;
    for (int i = blockIdx.x * blockDim.x + threadIdx.x; i < n_spots; i += stride)
        sw[i] = 0.0f;
}

// ---------------------------------------------------------------------------
// K2: degree counts (one thread per edge, grid-stride).
// ---------------------------------------------------------------------------
__global__ void degree_kernel(const int* __restrict__ user_idx,
                              const int* __restrict__ spot_idx,
                              int n_edges,
                              float* __restrict__ uw,
                              float* __restrict__ sw) {
    int stride = gridDim.x * blockDim.x;
    for (int e = blockIdx.x * blockDim.x + threadIdx.x; e < n_edges; e += stride) {
        atomicAdd(&uw[user_idx[e]], 1.0f);
        atomicAdd(&sw[spot_idx[e]], 1.0f);
    }
}

// ---------------------------------------------------------------------------
// K3: degree -> rsqrt(max(deg, 1e-6)), in place.
// ---------------------------------------------------------------------------
__global__ void rsqrt_kernel(float* __restrict__ uw, int n_users,
                             float* __restrict__ sw, int n_spots) {
    int stride = gridDim.x * blockDim.x;
    for (int i = blockIdx.x * blockDim.x + threadIdx.x; i < n_users; i += stride) {
        float d = uw[i];
        uw[i] = rsqrtf(d == 0.0f ? 1e-6f : d);
    }
    for (int i = blockIdx.x * blockDim.x + threadIdx.x; i < n_spots; i += stride) {
        float d = sw[i];
        sw[i] = rsqrtf(d == 0.0f ? 1e-6f : d);
    }
}

// ---------------------------------------------------------------------------
// K4: main scatter. Warp per edge; lane handles float2 column pair.
//   user_out[u] += spot_x[s] * inv_sqrt_spot[s]
//   spot_out[s] += user_x[u] * inv_sqrt_user[u]
// ---------------------------------------------------------------------------
__global__ void scatter_kernel(const float* __restrict__ user_x,
                               const float* __restrict__ spot_x,
                               const int* __restrict__ user_idx,
                               const int* __restrict__ spot_idx,
                               const float* __restrict__ uw,
                               const float* __restrict__ sw,
                               float* __restrict__ user_out,
                               float* __restrict__ spot_out,
                               int n_edges) {
    int warp  = (blockIdx.x * blockDim.x + threadIdx.x) >> 5;
    int lane  = threadIdx.x & 31;
    int nwarp = (gridDim.x * blockDim.x) >> 5;
    int col   = lane * 2;

    for (int e = warp; e < n_edges; e += nwarp) {
        int u = __ldg(&user_idx[e]);
        int s = __ldg(&spot_idx[e]);
        float wu = __ldg(&uw[u]);
        float ws = __ldg(&sw[s]);

        const float2 sx = *reinterpret_cast<const float2*>(spot_x + (size_t)s * FEAT + col);
        const float2 ux = *reinterpret_cast<const float2*>(user_x + (size_t)u * FEAT + col);

        float2 to_user = make_float2(sx.x * ws, sx.y * ws);
        float2 to_spot = make_float2(ux.x * wu, ux.y * wu);

        atomicAdd(reinterpret_cast<float2*>(user_out + (size_t)u * FEAT + col), to_user);
        atomicAdd(reinterpret_cast<float2*>(spot_out + (size_t)s * FEAT + col), to_spot);
    }
}

// ---------------------------------------------------------------------------
// K5: post-normalize by destination inv_sqrt degree.
// ---------------------------------------------------------------------------
__global__ void scale_kernel(float* __restrict__ user_out, int n_users,
                             float* __restrict__ spot_out, int n_spots,
                             const float* __restrict__ uw,
                             const float* __restrict__ sw) {
    int stride = gridDim.x * blockDim.x;
    int nu = n_users * FEAT;
    int ns = n_spots * FEAT;
    for (int i = blockIdx.x * blockDim.x + threadIdx.x; i < nu; i += stride)
        user_out[i] *= uw[i >> 6];
    for (int i = blockIdx.x * blockDim.x + threadIdx.x; i < ns; i += stride)
        spot_out[i] *= sw[i >> 6];
}

// ---------------------------------------------------------------------------
extern "C" void kernel_launch(void* const* d_in, const int* in_sizes, int n_in,
                              void* d_out, int out_size) {
    const float* user_x  = (const float*)d_in[0];
    const float* spot_x  = (const float*)d_in[1];
    const int*   user_idx = (const int*)d_in[2];
    const int*   spot_idx = (const int*)d_in[3];

    int n_users = in_sizes[0] / FEAT;
    int n_spots = in_sizes[1] / FEAT;
    int n_edges = in_sizes[2];

    float* out      = (float*)d_out;
    float* user_out = out;                            // [n_users, 64]
    float* spot_out = out + (size_t)n_users * FEAT;   // [n_spots, 64]

    float* uw;
    float* sw;
    cudaGetSymbolAddress((void**)&uw, g_user_w);
    cudaGetSymbolAddress((void**)&sw, g_spot_w);

    const int TPB = 256;
    // Enough blocks to cover the chip; grid-stride everywhere.
    const int BLK = 148 * 8;

    zero_kernel<<<BLK, TPB>>>(out, out_size, uw, n_users, sw, n_spots);
    degree_kernel<<<BLK, TPB>>>(user_idx, spot_idx, n_edges, uw, sw);
    rsqrt_kernel<<<BLK, TPB>>>(uw, n_users, sw, n_spots);
    // scatter: warp per edge, persistent grid
    scatter_kernel<<<148 * 16, TPB>>>(user_x, spot_x, user_idx, spot_idx,
                                      uw, sw, user_out, spot_out, n_edges);
    scale_kernel<<<BLK, TPB>>>(user_out, n_users, spot_out, n_spots, uw, sw);
}